// round 11
// baseline (speedup 1.0000x reference)
#include <cuda_runtime.h>
#include <cuda_bf16.h>
#include <cstdint>
#include <math.h>

// Problem dims (fixed by the dataset)
#define BB 16
#define TT 1024
#define DD 512
#define VV 5000
#define LL 128
#define SS 257              // 2L+1
#define MM (BB*TT)          // 16384 rows
#define NPAD 5120           // padded N
#define NTILES 20           // NPAD/256 (n-tiles of 256)
#define NT 160              // compact label-logit width (129 used, padded)
#define NEGF (-1e30f)
#define LOG2E 1.4426950408889634f
#define LN2F 0.6931471805599453f

// ------------------------- scratch (device globals; zero-initialized) ------
__device__ __nv_bfloat16 g_hsb[(size_t)MM * DD];          // 16.8 MB
__device__ __nv_bfloat16 g_Wb[(size_t)NPAD * DD];         // 5.2 MB (rows >=5000 stay zero)
__device__ __nv_bfloat16 g_Wc[(size_t)BB * NT * DD];      // gathered W cols
__device__ float g_biasc[BB * NT];
__device__ float g_lgc[(size_t)BB * TT * NT];             // compact label logits
__device__ float g_pmax[(size_t)MM * NTILES];
__device__ float g_psum[(size_t)MM * NTILES];
__device__ float g_lse[MM];
__device__ float g_lpext[(size_t)MM * SS];                // log2-domain ext log-probs
__device__ int   g_allow[BB * SS];
__device__ float g_loss[BB];

// ------------------------- helpers -----------------------------------------
__device__ __forceinline__ float fex2(float x) {
    float y; asm("ex2.approx.ftz.f32 %0, %1;" : "=f"(y) : "f"(x)); return y;
}
__device__ __forceinline__ float flg2(float x) {
    float y; asm("lg2.approx.f32 %0, %1;" : "=f"(y) : "f"(x)); return y;
}
#define CPA16(dst, src) \
    asm volatile("cp.async.cg.shared.global [%0], [%1], 16;\n" :: "r"(dst), "l"(src))
#define CP_COMMIT() asm volatile("cp.async.commit_group;\n" ::: "memory")
#define CP_WAIT0()  asm volatile("cp.async.wait_group 0;\n" ::: "memory")
#define CP_WAIT1()  asm volatile("cp.async.wait_group 1;\n" ::: "memory")

// ------------------------- conversions -------------------------------------
__global__ void conv_hs_kernel(const float* __restrict__ hs) {
    size_t i = (size_t)blockIdx.x * blockDim.x + threadIdx.x;   // over MM*DD/4
    float4 v = ((const float4*)hs)[i];
    __nv_bfloat162* o = reinterpret_cast<__nv_bfloat162*>(g_hsb) + i * 2;
    o[0] = __floats2bfloat162_rn(v.x, v.y);
    o[1] = __floats2bfloat162_rn(v.z, v.w);
}

// W (D,V) row-major -> Wb[n][k] bf16, transposed through shared tiles
__global__ void conv_w_kernel(const float* __restrict__ W) {
    __shared__ float tile[32][33];
    int nt = blockIdx.x * 32, kt = blockIdx.y * 32;
    int tx = threadIdx.x, ty = threadIdx.y;     // 32 x 8
    #pragma unroll
    for (int i = 0; i < 32; i += 8) {
        int k = kt + ty + i, n = nt + tx;
        tile[ty + i][tx] = (n < VV) ? W[(size_t)k * VV + n] : 0.f;
    }
    __syncthreads();
    #pragma unroll
    for (int i = 0; i < 32; i += 8) {
        int n = nt + ty + i, k = kt + tx;
        if (n < VV)
            g_Wb[(size_t)n * DD + k] = __float2bfloat16(tile[tx][ty + i]);
    }
}

// ------------------------- extended labels / allow -------------------------
__global__ void ext_kernel(const int* __restrict__ ys_pad) {
    int b = blockIdx.x;
    int s = threadIdx.x;
    if (s >= SS) return;
    int alw = 0;
    if (s & 1) {
        int i = s >> 1;
        alw = (s == 1) ? 1 : (ys_pad[b * LL + i] != ys_pad[b * LL + i - 1]);
    }
    g_allow[b * SS + s] = alw;
}

// gather W columns + bias for each batch's label set: j=0 -> blank, j=1+i -> ys[b][i]
__global__ void prep_wc_kernel(const int* __restrict__ ys_pad,
                               const float* __restrict__ bias) {
    int b = blockIdx.x, j = blockIdx.y;     // j in [0,129)
    int lab = (j == 0) ? 0 : ys_pad[b * LL + (j - 1)];
    const uint4* src = (const uint4*)(g_Wb + (size_t)lab * DD);
    uint4* dst = (uint4*)(g_Wc + ((size_t)b * NT + j) * DD);
    dst[threadIdx.x] = src[threadIdx.x];     // 64 threads x 16B = 512 bf16
    if (threadIdx.x == 0) g_biasc[b * NT + j] = bias[lab];
}

// ------------------------- mma / ldmatrix helpers --------------------------
__device__ __forceinline__ void mma_bf16(float* c, const uint32_t* a, const uint32_t* b) {
    asm volatile(
        "mma.sync.aligned.m16n8k16.row.col.f32.bf16.bf16.f32 "
        "{%0,%1,%2,%3}, {%4,%5,%6,%7}, {%8,%9}, {%0,%1,%2,%3};\n"
        : "+f"(c[0]), "+f"(c[1]), "+f"(c[2]), "+f"(c[3])
        : "r"(a[0]), "r"(a[1]), "r"(a[2]), "r"(a[3]), "r"(b[0]), "r"(b[1]));
}
__device__ __forceinline__ void ldsm_x4(uint32_t& r0, uint32_t& r1, uint32_t& r2, uint32_t& r3,
                                        uint32_t addr) {
    asm volatile("ldmatrix.sync.aligned.m8n8.x4.shared.b16 {%0,%1,%2,%3}, [%4];\n"
                 : "=r"(r0), "=r"(r1), "=r"(r2), "=r"(r3) : "r"(addr));
}

#define ROWB 48    // lgc kernel: 24 halves * 2 bytes per smem row
#define ROWB2 80   // main gemm: 40 halves * 2 bytes per smem row (32-k stage)

// ------------------------- main GEMM: lse partials only --------------------
// 128x256 block tile, 256 threads (2x4 warp grid, warp tile 64x64),
// 3-stage cp.async pipeline of 32-k stages. Dynamic smem.
#define SM_A_OFF 0
#define A_ST 10240            // 128 rows * 80 B
#define SM_B_OFF (3*A_ST)     // 30720
#define B_ST 20480            // 256 rows * 80 B
#define SM_SP (SM_B_OFF + 3*B_ST)   // 92160
#define SM_TOT (SM_SP + 4096)       // 96256

extern __shared__ char dsm[];

__device__ __forceinline__ void stage_gemm(uint32_t sb, int tid, int mBase, int nBase,
                                           int kt, int buf) {
    #pragma unroll
    for (int j = 0; j < 2; j++) {
        int i = tid * 2 + j, r = i >> 2, s = i & 3;
        CPA16(sb + SM_A_OFF + buf * A_ST + r * ROWB2 + s * 16,
              g_hsb + (size_t)(mBase + r) * DD + kt * 32 + s * 8);
    }
    #pragma unroll
    for (int j = 0; j < 4; j++) {
        int i = tid * 4 + j, r = i >> 2, s = i & 3;
        CPA16(sb + SM_B_OFF + buf * B_ST + r * ROWB2 + s * 16,
              g_Wb + (size_t)(nBase + r) * DD + kt * 32 + s * 8);
    }
    CP_COMMIT();
}

__global__ __launch_bounds__(256, 1) void gemm_kernel(const float* __restrict__ bias) {
    const int tid  = threadIdx.x;
    const int warp = tid >> 5, lane = tid & 31;
    const int wm = warp >> 2, wn = warp & 3;       // 2x4 warp grid
    const int g  = lane >> 2, cq = lane & 3;       // groupID / quad
    const int mBase = blockIdx.y * 128;
    const int nBase = blockIdx.x * 256;
    uint32_t sb = (uint32_t)__cvta_generic_to_shared(dsm);

    float* spmax = (float*)(dsm + SM_SP);          // [128][4]
    float* spsum = (float*)(dsm + SM_SP + 2048);   // [128][4]

    // ldmatrix per-lane offsets (within a stage buffer)
    const uint32_t aOff = (uint32_t)((wm * 64 + (lane & 15)) * ROWB2 + ((lane & 16) ? 16 : 0));
    const uint32_t bOff = (uint32_t)((wn * 64 + (lane & 7) + ((lane & 16) ? 8 : 0)) * ROWB2 +
                                     ((lane & 8) ? 16 : 0));

    stage_gemm(sb, tid, mBase, nBase, 0, 0);
    stage_gemm(sb, tid, mBase, nBase, 1, 1);

    float c[4][8][4];
    #pragma unroll
    for (int mi = 0; mi < 4; mi++)
        #pragma unroll
        for (int ni = 0; ni < 8; ni++)
            #pragma unroll
            for (int q = 0; q < 4; q++) c[mi][ni][q] = 0.f;

    #pragma unroll 1
    for (int kt = 0; kt < 16; kt++) {
        const int buf = kt % 3;
        if (kt < 15) { CP_WAIT1(); } else { CP_WAIT0(); }
        __syncthreads();
        if (kt + 2 < 16) stage_gemm(sb, tid, mBase, nBase, kt + 2, (kt + 2) % 3);

        const uint32_t aB = sb + SM_A_OFF + buf * A_ST + aOff;
        const uint32_t bB = sb + SM_B_OFF + buf * B_ST + bOff;
        #pragma unroll
        for (int ks = 0; ks < 2; ks++) {         // two 16-k sub-chunks
            const uint32_t ko = ks * 32;         // 16 halves = 32 bytes
            uint32_t af[4][4], bf[8][2];
            #pragma unroll
            for (int mi = 0; mi < 4; mi++)
                ldsm_x4(af[mi][0], af[mi][1], af[mi][2], af[mi][3],
                        aB + mi * 16 * ROWB2 + ko);
            #pragma unroll
            for (int p = 0; p < 4; p++)
                ldsm_x4(bf[2 * p][0], bf[2 * p][1], bf[2 * p + 1][0], bf[2 * p + 1][1],
                        bB + p * 16 * ROWB2 + ko);
            #pragma unroll
            for (int mi = 0; mi < 4; mi++)
                #pragma unroll
                for (int ni = 0; ni < 8; ni++)
                    mma_bf16(c[mi][ni], af[mi], bf[ni]);
        }
    }
    __syncthreads();

    // epilogue: bias + per-tile online-softmax partials (NO logits store)
    #pragma unroll
    for (int mi = 0; mi < 4; mi++) {
        const int mrow = wm * 64 + mi * 16 + g;
        float v0[16], v1[16];
        #pragma unroll
        for (int ni = 0; ni < 8; ni++) {
            int n = nBase + wn * 64 + ni * 8 + 2 * cq;
            bool ok = (n < VV);
            float b0 = ok ? bias[n] : 0.f;
            float b1 = ok ? bias[n + 1] : 0.f;
            v0[ni * 2]     = ok ? (c[mi][ni][0] + b0) : NEGF;
            v0[ni * 2 + 1] = ok ? (c[mi][ni][1] + b1) : NEGF;
            v1[ni * 2]     = ok ? (c[mi][ni][2] + b0) : NEGF;
            v1[ni * 2 + 1] = ok ? (c[mi][ni][3] + b1) : NEGF;
        }
        float mx0 = NEGF, mx1 = NEGF;
        #pragma unroll
        for (int j = 0; j < 16; j++) { mx0 = fmaxf(mx0, v0[j]); mx1 = fmaxf(mx1, v1[j]); }
        float s0 = 0.f, s1 = 0.f;
        #pragma unroll
        for (int j = 0; j < 16; j++) { s0 += __expf(v0[j] - mx0); s1 += __expf(v1[j] - mx1); }
        #pragma unroll
        for (int off = 1; off <= 2; off <<= 1) {
            float om = __shfl_xor_sync(0xffffffffu, mx0, off);
            float os = __shfl_xor_sync(0xffffffffu, s0, off);
            float nm = fmaxf(mx0, om);
            s0 = s0 * __expf(mx0 - nm) + os * __expf(om - nm); mx0 = nm;
            om = __shfl_xor_sync(0xffffffffu, mx1, off);
            os = __shfl_xor_sync(0xffffffffu, s1, off);
            nm = fmaxf(mx1, om);
            s1 = s1 * __expf(mx1 - nm) + os * __expf(om - nm); mx1 = nm;
        }
        if (cq == 0) {
            spmax[mrow * 4 + wn] = mx0; spsum[mrow * 4 + wn] = s0;
            spmax[(mrow + 8) * 4 + wn] = mx1; spsum[(mrow + 8) * 4 + wn] = s1;
        }
    }
    __syncthreads();
    if (tid < 128) {
        float mx = spmax[tid * 4], sm = spsum[tid * 4];
        #pragma unroll
        for (int w = 1; w < 4; w++) {
            float m2 = spmax[tid * 4 + w], s2 = spsum[tid * 4 + w];
            float nm = fmaxf(mx, m2);
            sm = sm * __expf(mx - nm) + s2 * __expf(m2 - nm); mx = nm;
        }
        g_pmax[(size_t)(mBase + tid) * NTILES + blockIdx.x] = mx;
        g_psum[(size_t)(mBase + tid) * NTILES + blockIdx.x] = sm;
    }
}

// ------------------------- combine partials -> row lse ---------------------
__global__ __launch_bounds__(256) void lsecombine_kernel() {
    int row = blockIdx.x * 8 + (threadIdx.x >> 5);
    int lane = threadIdx.x & 31;
    float mx = NEGF, sm = 0.f;
    if (lane < NTILES) {
        mx = g_pmax[(size_t)row * NTILES + lane];
        sm = g_psum[(size_t)row * NTILES + lane];
    }
    #pragma unroll
    for (int o = 16; o > 0; o >>= 1) {
        float m2 = __shfl_xor_sync(0xffffffffu, mx, o);
        float s2 = __shfl_xor_sync(0xffffffffu, sm, o);
        float nm = fmaxf(mx, m2);
        sm = sm * __expf(mx - nm) + s2 * __expf(m2 - nm); mx = nm;
    }
    if (lane == 0) g_lse[row] = mx + __logf(sm);
}

// ------------------------- small GEMM: compact label logits ----------------
// lgc[b][m][j] = hs[b,m,:] . Wc[b,j,:] + biasc[b][j]
__global__ __launch_bounds__(256) void lgc_kernel() {
    const int tid  = threadIdx.x;
    const int warp = tid >> 5, lane = tid & 31;
    const int wm = warp >> 1, wn = warp & 1;       // 4x2 warp grid
    const int g  = lane >> 2, cq = lane & 3;
    const int b = blockIdx.x;
    const int mBase = blockIdx.y * 128;

    __shared__ __nv_bfloat16 As[2][128][24];
    __shared__ __nv_bfloat16 Bs[2][NT][24];

    const int row = tid >> 1, half = tid & 1;
    const __nv_bfloat16* gA = g_hsb + ((size_t)b * TT + mBase + row) * DD + half * 8;
    const int bidx2 = tid + 256;
    const __nv_bfloat16* gB0 = g_Wc + ((size_t)b * NT + (tid >> 1)) * DD + (tid & 1) * 8;
    const __nv_bfloat16* gB1 = g_Wc + ((size_t)b * NT + (bidx2 >> 1)) * DD + (bidx2 & 1) * 8;

    uint32_t aBase0 = (uint32_t)__cvta_generic_to_shared(
        &As[0][wm * 32 + (lane & 15)][(lane & 16) ? 8 : 0]);
    uint32_t aBase1 = (uint32_t)__cvta_generic_to_shared(
        &As[1][wm * 32 + (lane & 15)][(lane & 16) ? 8 : 0]);
    uint32_t bBase0 = (uint32_t)__cvta_generic_to_shared(
        &Bs[0][wn * 80 + (lane & 7) + ((lane & 16) ? 8 : 0)][(lane & 8) ? 8 : 0]);
    uint32_t bBase1 = (uint32_t)__cvta_generic_to_shared(
        &Bs[1][wn * 80 + (lane & 7) + ((lane & 16) ? 8 : 0)][(lane & 8) ? 8 : 0]);

    {
        *(uint4*)&As[0][row][half * 8] = *(const uint4*)gA;
        *(uint4*)&Bs[0][tid >> 1][(tid & 1) * 8] = *(const uint4*)gB0;
        if (tid < 64)
            *(uint4*)&Bs[0][bidx2 >> 1][(bidx2 & 1) * 8] = *(const uint4*)gB1;
    }
    __syncthreads();

    float c[2][10][4];
    #pragma unroll
    for (int mi = 0; mi < 2; mi++)
        #pragma unroll
        for (int ni = 0; ni < 10; ni++)
            #pragma unroll
            for (int q = 0; q < 4; q++) c[mi][ni][q] = 0.f;

    #pragma unroll 1
    for (int kt = 0; kt < 32; kt++) {
        const int cur = kt & 1;
        uint4 na, nb0, nb1;
        if (kt < 31) {
            na  = *(const uint4*)(gA + (kt + 1) * 16);
            nb0 = *(const uint4*)(gB0 + (kt + 1) * 16);
            if (tid < 64) nb1 = *(const uint4*)(gB1 + (kt + 1) * 16);
        }
        const uint32_t aB = cur ? aBase1 : aBase0;
        const uint32_t bB = cur ? bBase1 : bBase0;
        uint32_t af[2][4], bf[10][2];
        #pragma unroll
        for (int mi = 0; mi < 2; mi++)
            ldsm_x4(af[mi][0], af[mi][1], af[mi][2], af[mi][3], aB + mi * 16 * ROWB);
        #pragma unroll
        for (int p = 0; p < 5; p++)
            ldsm_x4(bf[2 * p][0], bf[2 * p][1], bf[2 * p + 1][0], bf[2 * p + 1][1],
                    bB + p * 16 * ROWB);
        #pragma unroll
        for (int mi = 0; mi < 2; mi++)
            #pragma unroll
            for (int ni = 0; ni < 10; ni++)
                mma_bf16(c[mi][ni], af[mi], bf[ni]);

        if (kt < 31) {
            *(uint4*)&As[cur ^ 1][row][half * 8] = na;
            *(uint4*)&Bs[cur ^ 1][tid >> 1][(tid & 1) * 8] = nb0;
            if (tid < 64)
                *(uint4*)&Bs[cur ^ 1][bidx2 >> 1][(bidx2 & 1) * 8] = nb1;
        }
        __syncthreads();
    }

    float* lgb = g_lgc + ((size_t)b * TT + mBase) * NT;
    #pragma unroll
    for (int mi = 0; mi < 2; mi++) {
        int mrow = wm * 32 + mi * 16 + g;
        #pragma unroll
        for (int ni = 0; ni < 10; ni++) {
            int j = wn * 80 + ni * 8 + 2 * cq;
            float b0 = g_biasc[b * NT + j], b1 = g_biasc[b * NT + j + 1];
            *(float2*)&lgb[(size_t)mrow * NT + j] =
                make_float2(c[mi][ni][0] + b0, c[mi][ni][1] + b1);
            *(float2*)&lgb[(size_t)(mrow + 8) * NT + j] =
                make_float2(c[mi][ni][2] + b0, c[mi][ni][3] + b1);
        }
    }
}

// ------------------------- gather: lpext (log2 units) ----------------------
__global__ void gather_kernel() {
    int i = blockIdx.x * blockDim.x + threadIdx.x;
    if (i >= MM * SS) return;
    int rt = i / SS;                 // b*T + t
    int s  = i - rt * SS;
    int b  = rt >> 10;
    int t  = rt & 1023;
    int j  = (s & 1) ? (1 + (s >> 1)) : 0;
    float lp = g_lgc[((size_t)b * TT + t) * NT + j] - g_lse[rt];
    g_lpext[i] = lp * LOG2E;
}

// ------------------------- CTC forward recursion (log2 domain) -------------
__global__ __launch_bounds__(288) void ctc_kernel(const int* __restrict__ hlens,
                                                  const int* __restrict__ ys_lens) {
    const int b = blockIdx.x;
    const int s = threadIdx.x;
    const bool act = (s < SS);
    __shared__ float aS[2][SS + 4];   // index shift +2; pads hold NEGF

    const int hlen = hlens[b];
    const int alw = act ? g_allow[b * SS + s] : 0;
    const float* lpb = g_lpext + (size_t)b * TT * SS;

    if (s < 2) { aS[0][s] = NEGF; aS[1][s] = NEGF; }
    if (act) aS[0][s + 2] = (s < 2) ? lpb[s] : NEGF;
    __syncthreads();

    int cur = 0;
    float lp_c = act ? lpb[(size_t)SS + s] : 0.f;   // t = 1
    for (int t = 1; t < hlen; t++) {
        float lp_n = (act && t + 1 < hlen) ? lpb[(size_t)(t + 1) * SS + s] : 0.f;
        if (act) {
            float a1 = aS[cur][s + 2];
            float a2 = aS[cur][s + 1];
            float a3 = alw ? aS[cur][s] : NEGF;
            float m = fmaxf(fmaxf(a1, a2), a3);
            m = fmaxf(m, NEGF);
            float nv = m + flg2(fex2(a1 - m) + fex2(a2 - m) + fex2(a3 - m)) + lp_c;
            aS[cur ^ 1][s + 2] = nv;
        }
        __syncthreads();
        cur ^= 1;
        lp_c = lp_n;
    }

    if (s == 0) {
        int yl = ys_lens[b];
        int i1 = 2 * yl;
        int i2 = (i1 - 1 > 0) ? (i1 - 1) : 0;
        float A1 = aS[cur][i1 + 2];
        float A2 = aS[cur][i2 + 2];
        float m = fmaxf(A1, A2);
        float ll = (m + flg2(fex2(A1 - m) + fex2(A2 - m))) * LN2F;
        float loss = -ll;
        if (!isfinite(loss) || loss >= 1e29f) loss = 0.f;
        g_loss[b] = loss;
    }
}

// ------------------------- final reduction ---------------------------------
__global__ void final_kernel(const int* __restrict__ ys_lens, float* __restrict__ out) {
    int lane = threadIdx.x;
    float l  = (lane < BB) ? g_loss[lane] : 0.f;
    float yl = (lane < BB) ? (float)ys_lens[lane] : 0.f;
    #pragma unroll
    for (int o = 16; o > 0; o >>= 1) {
        l  += __shfl_down_sync(0xffffffffu, l, o);
        yl += __shfl_down_sync(0xffffffffu, yl, o);
    }
    if (lane == 0) out[0] = l / yl;
}

// ------------------------- launch ------------------------------------------
extern "C" void kernel_launch(void* const* d_in, const int* in_sizes, int n_in,
                              void* d_out, int out_size) {
    const float* hs      = (const float*)d_in[0];
    const int*   hlens   = (const int*)d_in[1];
    const int*   ys_pad  = (const int*)d_in[2];
    const int*   ys_lens = (const int*)d_in[3];
    const float* W       = (const float*)d_in[4];
    const float* bias    = (const float*)d_in[5];
    float* out = (float*)d_out;

    cudaFuncSetAttribute(gemm_kernel,
                         cudaFuncAttributeMaxDynamicSharedMemorySize, SM_TOT);

    conv_hs_kernel<<<(MM * DD / 4) / 256, 256>>>(hs);          // #1
    {
        dim3 wgrid((VV + 31) / 32, DD / 32);
        conv_w_kernel<<<wgrid, dim3(32, 8)>>>(W);              // #2
    }
    ext_kernel<<<BB, 288>>>(ys_pad);                           // #3

    dim3 ggrid(NPAD / 256, MM / 128);                          // #4  (profiled slot)
    gemm_kernel<<<ggrid, 256, SM_TOT>>>(bias);

    lsecombine_kernel<<<MM / 8, 256>>>();                      // #5

    prep_wc_kernel<<<dim3(BB, 129), 64>>>(ys_pad, bias);       // #6

    lgc_kernel<<<dim3(BB, TT / 128), 256>>>();                 // #7

    int total = MM * SS;
    gather_kernel<<<(total + 255) / 256, 256>>>();             // #8

    ctc_kernel<<<BB, 288>>>(hlens, ys_lens);                   // #9
    final_kernel<<<1, 32>>>(ys_lens, out);                     // #10
}

// round 12
// speedup vs baseline: 1.1066x; 1.1066x over previous
#include <cuda_runtime.h>
#include <cuda_bf16.h>
#include <cstdint>
#include <math.h>

// Problem dims (fixed by the dataset)
#define BB 16
#define TT 1024
#define DD 512
#define VV 5000
#define LL 128
#define SS 257              // 2L+1
#define MM (BB*TT)          // 16384 rows
#define NPAD 5120           // padded N
#define NTILES 20           // NPAD/256 (n-tiles of 256)
#define NT 160              // compact label-logit width (129 used, padded)
#define NEGF (-1e30f)
#define LOG2E 1.4426950408889634f
#define LN2F 0.6931471805599453f

// ------------------------- scratch (device globals; zero-initialized) ------
__device__ __nv_bfloat16 g_hsb[(size_t)MM * DD];          // 16.8 MB
__device__ __nv_bfloat16 g_Wb[(size_t)NPAD * DD];         // 5.2 MB (rows >=5000 stay zero)
__device__ __nv_bfloat16 g_Wc[(size_t)BB * NT * DD];      // gathered W cols
__device__ float g_biasc[BB * NT];
__device__ float g_lgc[(size_t)BB * TT * NT];             // compact label logits
__device__ float g_pmax[(size_t)MM * NTILES];
__device__ float g_psum[(size_t)MM * NTILES];
__device__ float g_lse[MM];
__device__ float g_lpext[(size_t)MM * SS];                // log2-domain ext log-probs
__device__ int   g_allow[BB * SS];
__device__ float g_loss[BB];

// ------------------------- helpers -----------------------------------------
__device__ __forceinline__ float fex2(float x) {
    float y; asm("ex2.approx.ftz.f32 %0, %1;" : "=f"(y) : "f"(x)); return y;
}
__device__ __forceinline__ float flg2(float x) {
    float y; asm("lg2.approx.f32 %0, %1;" : "=f"(y) : "f"(x)); return y;
}
#define CPA16(dst, src) \
    asm volatile("cp.async.cg.shared.global [%0], [%1], 16;\n" :: "r"(dst), "l"(src))
#define CP_COMMIT() asm volatile("cp.async.commit_group;\n" ::: "memory")
#define CP_WAIT0()  asm volatile("cp.async.wait_group 0;\n" ::: "memory")
#define CP_WAIT1()  asm volatile("cp.async.wait_group 1;\n" ::: "memory")

// ------------------------- conversions -------------------------------------
__global__ void conv_hs_kernel(const float* __restrict__ hs) {
    size_t i = (size_t)blockIdx.x * blockDim.x + threadIdx.x;   // over MM*DD/4
    float4 v = ((const float4*)hs)[i];
    __nv_bfloat162* o = reinterpret_cast<__nv_bfloat162*>(g_hsb) + i * 2;
    o[0] = __floats2bfloat162_rn(v.x, v.y);
    o[1] = __floats2bfloat162_rn(v.z, v.w);
}

// W (D,V) row-major -> Wb[n][k] bf16, transposed through shared tiles
__global__ void conv_w_kernel(const float* __restrict__ W) {
    __shared__ float tile[32][33];
    int nt = blockIdx.x * 32, kt = blockIdx.y * 32;
    int tx = threadIdx.x, ty = threadIdx.y;     // 32 x 8
    #pragma unroll
    for (int i = 0; i < 32; i += 8) {
        int k = kt + ty + i, n = nt + tx;
        tile[ty + i][tx] = (n < VV) ? W[(size_t)k * VV + n] : 0.f;
    }
    __syncthreads();
    #pragma unroll
    for (int i = 0; i < 32; i += 8) {
        int n = nt + ty + i, k = kt + tx;
        if (n < VV)
            g_Wb[(size_t)n * DD + k] = __float2bfloat16(tile[tx][ty + i]);
    }
}

// ------------------------- extended labels / allow -------------------------
__global__ void ext_kernel(const int* __restrict__ ys_pad) {
    int b = blockIdx.x;
    int s = threadIdx.x;
    if (s >= SS) return;
    int alw = 0;
    if (s & 1) {
        int i = s >> 1;
        alw = (s == 1) ? 1 : (ys_pad[b * LL + i] != ys_pad[b * LL + i - 1]);
    }
    g_allow[b * SS + s] = alw;
}

// gather W columns + bias for each batch's label set: j=0 -> blank, j=1+i -> ys[b][i]
__global__ void prep_wc_kernel(const int* __restrict__ ys_pad,
                               const float* __restrict__ bias) {
    int b = blockIdx.x, j = blockIdx.y;     // j in [0,129)
    int lab = (j == 0) ? 0 : ys_pad[b * LL + (j - 1)];
    const uint4* src = (const uint4*)(g_Wb + (size_t)lab * DD);
    uint4* dst = (uint4*)(g_Wc + ((size_t)b * NT + j) * DD);
    dst[threadIdx.x] = src[threadIdx.x];     // 64 threads x 16B = 512 bf16
    if (threadIdx.x == 0) g_biasc[b * NT + j] = bias[lab];
}

// ------------------------- mma / ldmatrix helpers --------------------------
__device__ __forceinline__ void mma_bf16(float* c, const uint32_t* a, const uint32_t* b) {
    asm volatile(
        "mma.sync.aligned.m16n8k16.row.col.f32.bf16.bf16.f32 "
        "{%0,%1,%2,%3}, {%4,%5,%6,%7}, {%8,%9}, {%0,%1,%2,%3};\n"
        : "+f"(c[0]), "+f"(c[1]), "+f"(c[2]), "+f"(c[3])
        : "r"(a[0]), "r"(a[1]), "r"(a[2]), "r"(a[3]), "r"(b[0]), "r"(b[1]));
}
__device__ __forceinline__ void ldsm_x4(uint32_t& r0, uint32_t& r1, uint32_t& r2, uint32_t& r3,
                                        uint32_t addr) {
    asm volatile("ldmatrix.sync.aligned.m8n8.x4.shared.b16 {%0,%1,%2,%3}, [%4];\n"
                 : "=r"(r0), "=r"(r1), "=r"(r2), "=r"(r3) : "r"(addr));
}

#define ROWB 48    // lgc kernel: 24 halves * 2 bytes per smem row
#define ROWB2 80   // main gemm: 40 halves * 2 bytes per smem row (32-k stage)

// ------------------------- main GEMM: lse partials only --------------------
// 128x256 block tile, 512 threads (2x8 warp grid, warp tile 64x32),
// 3-stage cp.async pipeline of 32-k stages. Dynamic smem.
#define SM_A_OFF 0
#define A_ST 10240            // 128 rows * 80 B
#define SM_B_OFF (3*A_ST)     // 30720
#define B_ST 20480            // 256 rows * 80 B
#define SM_SP (SM_B_OFF + 3*B_ST)   // 92160
#define SM_TOT (SM_SP + 8192)       // 100352

extern __shared__ char dsm[];

__device__ __forceinline__ void stage_gemm(uint32_t sb, int tid, int mBase, int nBase,
                                           int kt, int buf) {
    // A: 512 chunks of 16B -> 1 per thread
    {
        int r = tid >> 2, s = tid & 3;
        CPA16(sb + SM_A_OFF + buf * A_ST + r * ROWB2 + s * 16,
              g_hsb + (size_t)(mBase + r) * DD + kt * 32 + s * 8);
    }
    // B: 1024 chunks of 16B -> 2 per thread
    #pragma unroll
    for (int j = 0; j < 2; j++) {
        int i = tid * 2 + j, r = i >> 2, s = i & 3;
        CPA16(sb + SM_B_OFF + buf * B_ST + r * ROWB2 + s * 16,
              g_Wb + (size_t)(nBase + r) * DD + kt * 32 + s * 8);
    }
    CP_COMMIT();
}

__global__ __launch_bounds__(512, 1) void gemm_kernel(const float* __restrict__ bias) {
    const int tid  = threadIdx.x;
    const int warp = tid >> 5, lane = tid & 31;
    const int wm = warp >> 3, wn = warp & 7;       // 2x8 warp grid
    const int g  = lane >> 2, cq = lane & 3;       // groupID / quad
    const int mBase = blockIdx.y * 128;
    const int nBase = blockIdx.x * 256;
    uint32_t sb = (uint32_t)__cvta_generic_to_shared(dsm);

    float* spmax = (float*)(dsm + SM_SP);          // [128][8]
    float* spsum = (float*)(dsm + SM_SP + 4096);   // [128][8]

    // ldmatrix per-lane offsets (within a stage buffer)
    const uint32_t aOff = (uint32_t)((wm * 64 + (lane & 15)) * ROWB2 + ((lane & 16) ? 16 : 0));
    const uint32_t bOff = (uint32_t)((wn * 32 + (lane & 7) + ((lane & 16) ? 8 : 0)) * ROWB2 +
                                     ((lane & 8) ? 16 : 0));

    stage_gemm(sb, tid, mBase, nBase, 0, 0);
    stage_gemm(sb, tid, mBase, nBase, 1, 1);

    float c[4][4][4];
    #pragma unroll
    for (int mi = 0; mi < 4; mi++)
        #pragma unroll
        for (int ni = 0; ni < 4; ni++)
            #pragma unroll
            for (int q = 0; q < 4; q++) c[mi][ni][q] = 0.f;

    #pragma unroll 1
    for (int kt = 0; kt < 16; kt++) {
        const int buf = kt % 3;
        if (kt < 15) { CP_WAIT1(); } else { CP_WAIT0(); }
        __syncthreads();
        if (kt + 2 < 16) stage_gemm(sb, tid, mBase, nBase, kt + 2, (kt + 2) % 3);

        const uint32_t aB = sb + SM_A_OFF + buf * A_ST + aOff;
        const uint32_t bB = sb + SM_B_OFF + buf * B_ST + bOff;
        #pragma unroll
        for (int ks = 0; ks < 2; ks++) {         // two 16-k sub-chunks
            const uint32_t ko = ks * 32;         // 16 halves = 32 bytes
            uint32_t af[4][4], bf[4][2];
            #pragma unroll
            for (int mi = 0; mi < 4; mi++)
                ldsm_x4(af[mi][0], af[mi][1], af[mi][2], af[mi][3],
                        aB + mi * 16 * ROWB2 + ko);
            #pragma unroll
            for (int p = 0; p < 2; p++)
                ldsm_x4(bf[2 * p][0], bf[2 * p][1], bf[2 * p + 1][0], bf[2 * p + 1][1],
                        bB + p * 16 * ROWB2 + ko);
            #pragma unroll
            for (int mi = 0; mi < 4; mi++)
                #pragma unroll
                for (int ni = 0; ni < 4; ni++)
                    mma_bf16(c[mi][ni], af[mi], bf[ni]);
        }
    }
    __syncthreads();

    // epilogue: bias + per-tile online-softmax partials (NO logits store)
    #pragma unroll
    for (int mi = 0; mi < 4; mi++) {
        const int mrow = wm * 64 + mi * 16 + g;
        float v0[8], v1[8];
        #pragma unroll
        for (int ni = 0; ni < 4; ni++) {
            int n = nBase + wn * 32 + ni * 8 + 2 * cq;
            bool ok = (n < VV);
            float b0 = ok ? bias[n] : 0.f;
            float b1 = ok ? bias[n + 1] : 0.f;
            v0[ni * 2]     = ok ? (c[mi][ni][0] + b0) : NEGF;
            v0[ni * 2 + 1] = ok ? (c[mi][ni][1] + b1) : NEGF;
            v1[ni * 2]     = ok ? (c[mi][ni][2] + b0) : NEGF;
            v1[ni * 2 + 1] = ok ? (c[mi][ni][3] + b1) : NEGF;
        }
        float mx0 = NEGF, mx1 = NEGF;
        #pragma unroll
        for (int j = 0; j < 8; j++) { mx0 = fmaxf(mx0, v0[j]); mx1 = fmaxf(mx1, v1[j]); }
        float s0 = 0.f, s1 = 0.f;
        #pragma unroll
        for (int j = 0; j < 8; j++) { s0 += __expf(v0[j] - mx0); s1 += __expf(v1[j] - mx1); }
        #pragma unroll
        for (int off = 1; off <= 2; off <<= 1) {
            float om = __shfl_xor_sync(0xffffffffu, mx0, off);
            float os = __shfl_xor_sync(0xffffffffu, s0, off);
            float nm = fmaxf(mx0, om);
            s0 = s0 * __expf(mx0 - nm) + os * __expf(om - nm); mx0 = nm;
            om = __shfl_xor_sync(0xffffffffu, mx1, off);
            os = __shfl_xor_sync(0xffffffffu, s1, off);
            nm = fmaxf(mx1, om);
            s1 = s1 * __expf(mx1 - nm) + os * __expf(om - nm); mx1 = nm;
        }
        if (cq == 0) {
            spmax[mrow * 8 + wn] = mx0; spsum[mrow * 8 + wn] = s0;
            spmax[(mrow + 8) * 8 + wn] = mx1; spsum[(mrow + 8) * 8 + wn] = s1;
        }
    }
    __syncthreads();
    if (tid < 128) {
        float mx = spmax[tid * 8], sm = spsum[tid * 8];
        #pragma unroll
        for (int w = 1; w < 8; w++) {
            float m2 = spmax[tid * 8 + w], s2 = spsum[tid * 8 + w];
            float nm = fmaxf(mx, m2);
            sm = sm * __expf(mx - nm) + s2 * __expf(m2 - nm); mx = nm;
        }
        g_pmax[(size_t)(mBase + tid) * NTILES + blockIdx.x] = mx;
        g_psum[(size_t)(mBase + tid) * NTILES + blockIdx.x] = sm;
    }
}

// ------------------------- combine partials -> row lse ---------------------
__global__ __launch_bounds__(256) void lsecombine_kernel() {
    int row = blockIdx.x * 8 + (threadIdx.x >> 5);
    int lane = threadIdx.x & 31;
    float mx = NEGF, sm = 0.f;
    if (lane < NTILES) {
        mx = g_pmax[(size_t)row * NTILES + lane];
        sm = g_psum[(size_t)row * NTILES + lane];
    }
    #pragma unroll
    for (int o = 16; o > 0; o >>= 1) {
        float m2 = __shfl_xor_sync(0xffffffffu, mx, o);
        float s2 = __shfl_xor_sync(0xffffffffu, sm, o);
        float nm = fmaxf(mx, m2);
        sm = sm * __expf(mx - nm) + s2 * __expf(m2 - nm); mx = nm;
    }
    if (lane == 0) g_lse[row] = mx + __logf(sm);
}

// ------------------------- small GEMM: compact label logits ----------------
// lgc[b][m][j] = hs[b,m,:] . Wc[b,j,:] + biasc[b][j]
__global__ __launch_bounds__(256) void lgc_kernel() {
    const int tid  = threadIdx.x;
    const int warp = tid >> 5, lane = tid & 31;
    const int wm = warp >> 1, wn = warp & 1;       // 4x2 warp grid
    const int g  = lane >> 2, cq = lane & 3;
    const int b = blockIdx.x;
    const int mBase = blockIdx.y * 128;

    __shared__ __nv_bfloat16 As[2][128][24];
    __shared__ __nv_bfloat16 Bs[2][NT][24];

    const int row = tid >> 1, half = tid & 1;
    const __nv_bfloat16* gA = g_hsb + ((size_t)b * TT + mBase + row) * DD + half * 8;
    const int bidx2 = tid + 256;
    const __nv_bfloat16* gB0 = g_Wc + ((size_t)b * NT + (tid >> 1)) * DD + (tid & 1) * 8;
    const __nv_bfloat16* gB1 = g_Wc + ((size_t)b * NT + (bidx2 >> 1)) * DD + (bidx2 & 1) * 8;

    uint32_t aBase0 = (uint32_t)__cvta_generic_to_shared(
        &As[0][wm * 32 + (lane & 15)][(lane & 16) ? 8 : 0]);
    uint32_t aBase1 = (uint32_t)__cvta_generic_to_shared(
        &As[1][wm * 32 + (lane & 15)][(lane & 16) ? 8 : 0]);
    uint32_t bBase0 = (uint32_t)__cvta_generic_to_shared(
        &Bs[0][wn * 80 + (lane & 7) + ((lane & 16) ? 8 : 0)][(lane & 8) ? 8 : 0]);
    uint32_t bBase1 = (uint32_t)__cvta_generic_to_shared(
        &Bs[1][wn * 80 + (lane & 7) + ((lane & 16) ? 8 : 0)][(lane & 8) ? 8 : 0]);

    {
        *(uint4*)&As[0][row][half * 8] = *(const uint4*)gA;
        *(uint4*)&Bs[0][tid >> 1][(tid & 1) * 8] = *(const uint4*)gB0;
        if (tid < 64)
            *(uint4*)&Bs[0][bidx2 >> 1][(bidx2 & 1) * 8] = *(const uint4*)gB1;
    }
    __syncthreads();

    float c[2][10][4];
    #pragma unroll
    for (int mi = 0; mi < 2; mi++)
        #pragma unroll
        for (int ni = 0; ni < 10; ni++)
            #pragma unroll
            for (int q = 0; q < 4; q++) c[mi][ni][q] = 0.f;

    #pragma unroll 1
    for (int kt = 0; kt < 32; kt++) {
        const int cur = kt & 1;
        uint4 na, nb0, nb1;
        if (kt < 31) {
            na  = *(const uint4*)(gA + (kt + 1) * 16);
            nb0 = *(const uint4*)(gB0 + (kt + 1) * 16);
            if (tid < 64) nb1 = *(const uint4*)(gB1 + (kt + 1) * 16);
        }
        const uint32_t aB = cur ? aBase1 : aBase0;
        const uint32_t bB = cur ? bBase1 : bBase0;
        uint32_t af[2][4], bf[10][2];
        #pragma unroll
        for (int mi = 0; mi < 2; mi++)
            ldsm_x4(af[mi][0], af[mi][1], af[mi][2], af[mi][3], aB + mi * 16 * ROWB);
        #pragma unroll
        for (int p = 0; p < 5; p++)
            ldsm_x4(bf[2 * p][0], bf[2 * p][1], bf[2 * p + 1][0], bf[2 * p + 1][1],
                    bB + p * 16 * ROWB);
        #pragma unroll
        for (int mi = 0; mi < 2; mi++)
            #pragma unroll
            for (int ni = 0; ni < 10; ni++)
                mma_bf16(c[mi][ni], af[mi], bf[ni]);

        if (kt < 31) {
            *(uint4*)&As[cur ^ 1][row][half * 8] = na;
            *(uint4*)&Bs[cur ^ 1][tid >> 1][(tid & 1) * 8] = nb0;
            if (tid < 64)
                *(uint4*)&Bs[cur ^ 1][bidx2 >> 1][(bidx2 & 1) * 8] = nb1;
        }
        __syncthreads();
    }

    float* lgb = g_lgc + ((size_t)b * TT + mBase) * NT;
    #pragma unroll
    for (int mi = 0; mi < 2; mi++) {
        int mrow = wm * 32 + mi * 16 + g;
        #pragma unroll
        for (int ni = 0; ni < 10; ni++) {
            int j = wn * 80 + ni * 8 + 2 * cq;
            float b0 = g_biasc[b * NT + j], b1 = g_biasc[b * NT + j + 1];
            *(float2*)&lgb[(size_t)mrow * NT + j] =
                make_float2(c[mi][ni][0] + b0, c[mi][ni][1] + b1);
            *(float2*)&lgb[(size_t)(mrow + 8) * NT + j] =
                make_float2(c[mi][ni][2] + b0, c[mi][ni][3] + b1);
        }
    }
}

// ------------------------- gather: lpext (log2 units) ----------------------
__global__ void gather_kernel() {
    int i = blockIdx.x * blockDim.x + threadIdx.x;
    if (i >= MM * SS) return;
    int rt = i / SS;                 // b*T + t
    int s  = i - rt * SS;
    int b  = rt >> 10;
    int t  = rt & 1023;
    int j  = (s & 1) ? (1 + (s >> 1)) : 0;
    float lp = g_lgc[((size_t)b * TT + t) * NT + j] - g_lse[rt];
    g_lpext[i] = lp * LOG2E;
}

// ------------------------- CTC forward recursion (log2 domain) -------------
__global__ __launch_bounds__(288) void ctc_kernel(const int* __restrict__ hlens,
                                                  const int* __restrict__ ys_lens) {
    const int b = blockIdx.x;
    const int s = threadIdx.x;
    const bool act = (s < SS);
    __shared__ float aS[2][SS + 4];   // index shift +2; pads hold NEGF

    const int hlen = hlens[b];
    const int alw = act ? g_allow[b * SS + s] : 0;
    const float* lpb = g_lpext + (size_t)b * TT * SS;

    if (s < 2) { aS[0][s] = NEGF; aS[1][s] = NEGF; }
    if (act) aS[0][s + 2] = (s < 2) ? lpb[s] : NEGF;
    __syncthreads();

    int cur = 0;
    float lp_c = act ? lpb[(size_t)SS + s] : 0.f;   // t = 1
    for (int t = 1; t < hlen; t++) {
        float lp_n = (act && t + 1 < hlen) ? lpb[(size_t)(t + 1) * SS + s] : 0.f;
        if (act) {
            float a1 = aS[cur][s + 2];
            float a2 = aS[cur][s + 1];
            float a3 = alw ? aS[cur][s] : NEGF;
            float m = fmaxf(fmaxf(a1, a2), a3);
            m = fmaxf(m, NEGF);
            float nv = m + flg2(fex2(a1 - m) + fex2(a2 - m) + fex2(a3 - m)) + lp_c;
            aS[cur ^ 1][s + 2] = nv;
        }
        __syncthreads();
        cur ^= 1;
        lp_c = lp_n;
    }

    if (s == 0) {
        int yl = ys_lens[b];
        int i1 = 2 * yl;
        int i2 = (i1 - 1 > 0) ? (i1 - 1) : 0;
        float A1 = aS[cur][i1 + 2];
        float A2 = aS[cur][i2 + 2];
        float m = fmaxf(A1, A2);
        float ll = (m + flg2(fex2(A1 - m) + fex2(A2 - m))) * LN2F;
        float loss = -ll;
        if (!isfinite(loss) || loss >= 1e29f) loss = 0.f;
        g_loss[b] = loss;
    }
}

// ------------------------- final reduction ---------------------------------
__global__ void final_kernel(const int* __restrict__ ys_lens, float* __restrict__ out) {
    int lane = threadIdx.x;
    float l  = (lane < BB) ? g_loss[lane] : 0.f;
    float yl = (lane < BB) ? (float)ys_lens[lane] : 0.f;
    #pragma unroll
    for (int o = 16; o > 0; o >>= 1) {
        l  += __shfl_down_sync(0xffffffffu, l, o);
        yl += __shfl_down_sync(0xffffffffu, yl, o);
    }
    if (lane == 0) out[0] = l / yl;
}

// ------------------------- launch ------------------------------------------
extern "C" void kernel_launch(void* const* d_in, const int* in_sizes, int n_in,
                              void* d_out, int out_size) {
    const float* hs      = (const float*)d_in[0];
    const int*   hlens   = (const int*)d_in[1];
    const int*   ys_pad  = (const int*)d_in[2];
    const int*   ys_lens = (const int*)d_in[3];
    const float* W       = (const float*)d_in[4];
    const float* bias    = (const float*)d_in[5];
    float* out = (float*)d_out;

    cudaFuncSetAttribute(gemm_kernel,
                         cudaFuncAttributeMaxDynamicSharedMemorySize, SM_TOT);

    conv_hs_kernel<<<(MM * DD / 4) / 256, 256>>>(hs);          // #1
    {
        dim3 wgrid((VV + 31) / 32, DD / 32);
        conv_w_kernel<<<wgrid, dim3(32, 8)>>>(W);              // #2
    }
    ext_kernel<<<BB, 288>>>(ys_pad);                           // #3

    dim3 ggrid(NPAD / 256, MM / 128);                          // #4  (profiled slot)
    gemm_kernel<<<ggrid, 512, SM_TOT>>>(bias);

    lsecombine_kernel<<<MM / 8, 256>>>();                      // #5

    prep_wc_kernel<<<dim3(BB, 129), 64>>>(ys_pad, bias);       // #6

    lgc_kernel<<<dim3(BB, TT / 128), 256>>>();                 // #7

    int total = MM * SS;
    gather_kernel<<<(total + 255) / 256, 256>>>();             // #8

    ctc_kernel<<<BB, 288>>>(hlens, ys_lens);                   // #9
    final_kernel<<<1, 32>>>(ys_lens, out);                     // #10
}

// round 13
// speedup vs baseline: 1.2342x; 1.1153x over previous
#include <cuda_runtime.h>
#include <cuda_bf16.h>
#include <cstdint>
#include <math.h>

// Problem dims (fixed by the dataset)
#define BB 16
#define TT 1024
#define DD 512
#define VV 5000
#define LL 128
#define SS 257              // 2L+1
#define MM (BB*TT)          // 16384 rows
#define NPAD 5120           // padded N
#define NTILES 20           // NPAD/256 (n-tiles of 256)
#define NT 160              // compact label-logit width (129 used, padded)
#define NEGF (-1e30f)
#define LOG2E 1.4426950408889634f
#define LN2F 0.6931471805599453f

// ------------------------- scratch (device globals; zero-initialized) ------
__device__ __nv_bfloat16 g_hsb[(size_t)MM * DD];          // 16.8 MB
__device__ __nv_bfloat16 g_Wb[(size_t)NPAD * DD];         // 5.2 MB (rows >=5000 stay zero)
__device__ __nv_bfloat16 g_Wc[(size_t)BB * NT * DD];      // gathered W cols
__device__ float g_biasc[BB * NT];
__device__ float g_lgc[(size_t)BB * TT * NT];             // compact label logits
__device__ float g_pmax[(size_t)MM * NTILES];
__device__ float g_psum[(size_t)MM * NTILES];
__device__ float g_lse[MM];
__device__ int   g_allow[BB * SS];
__device__ float g_loss[BB];

// ------------------------- helpers -----------------------------------------
__device__ __forceinline__ float fex2(float x) {
    float y; asm("ex2.approx.ftz.f32 %0, %1;" : "=f"(y) : "f"(x)); return y;
}
__device__ __forceinline__ float flg2(float x) {
    float y; asm("lg2.approx.f32 %0, %1;" : "=f"(y) : "f"(x)); return y;
}

// ------------------------- conversions -------------------------------------
__global__ void conv_hs_kernel(const float* __restrict__ hs) {
    size_t i = (size_t)blockIdx.x * blockDim.x + threadIdx.x;   // over MM*DD/4
    float4 v = ((const float4*)hs)[i];
    __nv_bfloat162* o = reinterpret_cast<__nv_bfloat162*>(g_hsb) + i * 2;
    o[0] = __floats2bfloat162_rn(v.x, v.y);
    o[1] = __floats2bfloat162_rn(v.z, v.w);
}

// W (D,V) row-major -> Wb[n][k] bf16, transposed through shared tiles
__global__ void conv_w_kernel(const float* __restrict__ W) {
    __shared__ float tile[32][33];
    int nt = blockIdx.x * 32, kt = blockIdx.y * 32;
    int tx = threadIdx.x, ty = threadIdx.y;     // 32 x 8
    #pragma unroll
    for (int i = 0; i < 32; i += 8) {
        int k = kt + ty + i, n = nt + tx;
        tile[ty + i][tx] = (n < VV) ? W[(size_t)k * VV + n] : 0.f;
    }
    __syncthreads();
    #pragma unroll
    for (int i = 0; i < 32; i += 8) {
        int n = nt + ty + i, k = kt + tx;
        if (n < VV)
            g_Wb[(size_t)n * DD + k] = __float2bfloat16(tile[tx][ty + i]);
    }
}

// ------------------------- extended labels / allow -------------------------
__global__ void ext_kernel(const int* __restrict__ ys_pad) {
    int b = blockIdx.x;
    int s = threadIdx.x;
    if (s >= SS) return;
    int alw = 0;
    if (s & 1) {
        int i = s >> 1;
        alw = (s == 1) ? 1 : (ys_pad[b * LL + i] != ys_pad[b * LL + i - 1]);
    }
    g_allow[b * SS + s] = alw;
}

// gather W columns + bias for each batch's label set: j=0 -> blank, j=1+i -> ys[b][i]
__global__ void prep_wc_kernel(const int* __restrict__ ys_pad,
                               const float* __restrict__ bias) {
    int b = blockIdx.x, j = blockIdx.y;     // j in [0,129)
    int lab = (j == 0) ? 0 : ys_pad[b * LL + (j - 1)];
    const uint4* src = (const uint4*)(g_Wb + (size_t)lab * DD);
    uint4* dst = (uint4*)(g_Wc + ((size_t)b * NT + j) * DD);
    dst[threadIdx.x] = src[threadIdx.x];     // 64 threads x 16B = 512 bf16
    if (threadIdx.x == 0) g_biasc[b * NT + j] = bias[lab];
}

// ------------------------- mma / ldmatrix helpers --------------------------
__device__ __forceinline__ void mma_bf16(float* c, const uint32_t* a, const uint32_t* b) {
    asm volatile(
        "mma.sync.aligned.m16n8k16.row.col.f32.bf16.bf16.f32 "
        "{%0,%1,%2,%3}, {%4,%5,%6,%7}, {%8,%9}, {%0,%1,%2,%3};\n"
        : "+f"(c[0]), "+f"(c[1]), "+f"(c[2]), "+f"(c[3])
        : "r"(a[0]), "r"(a[1]), "r"(a[2]), "r"(a[3]), "r"(b[0]), "r"(b[1]));
}
__device__ __forceinline__ void ldsm_x4(uint32_t& r0, uint32_t& r1, uint32_t& r2, uint32_t& r3,
                                        uint32_t addr) {
    asm volatile("ldmatrix.sync.aligned.m8n8.x4.shared.b16 {%0,%1,%2,%3}, [%4];\n"
                 : "=r"(r0), "=r"(r1), "=r"(r2), "=r"(r3) : "r"(addr));
}

#define ROWB 48    // lgc kernel: 24 halves * 2 bytes per smem row
#define ROWB2 80   // main gemm: 40 halves * 2 bytes per smem row (32-k stage)

// ------------------------- main GEMM: lse partials only --------------------
// 128x256 block tile, 512 threads (2x8 warp grid, warp tile 64x32),
// 32-k double-buffered stages, register staging (proven R8 config).
__global__ __launch_bounds__(512) void gemm_kernel(const float* __restrict__ bias) {
    const int tid  = threadIdx.x;
    const int warp = tid >> 5, lane = tid & 31;
    const int wm = warp >> 3, wn = warp & 7;       // 2x8 warp grid
    const int g  = lane >> 2, cq = lane & 3;       // groupID / quad
    const int mBase = blockIdx.y * 128;
    const int nBase = blockIdx.x * 256;

    __shared__ __nv_bfloat16 As[2][128][40];       // 32 k + 8 pad halves
    __shared__ __nv_bfloat16 Bs[2][256][40];
    __shared__ float spmax[128][8];
    __shared__ float spsum[128][8];

    // staging: A one 16B seg per thread, B two
    const int rowA = tid >> 2, segA = tid & 3;     // 128 rows x 4 segs
    const __nv_bfloat16* gA  = g_hsb + (size_t)(mBase + rowA) * DD + segA * 8;
    const __nv_bfloat16* gB0 = g_Wb  + (size_t)(nBase + rowA) * DD + segA * 8;
    const __nv_bfloat16* gB1 = g_Wb  + (size_t)(nBase + rowA + 128) * DD + segA * 8;

    // ldmatrix base addresses (per lane); mi/p and k-sub-chunk offsets in-loop
    uint32_t aBase0 = (uint32_t)__cvta_generic_to_shared(
        &As[0][wm * 64 + (lane & 15)][(lane & 16) ? 8 : 0]);
    uint32_t aBase1 = (uint32_t)__cvta_generic_to_shared(
        &As[1][wm * 64 + (lane & 15)][(lane & 16) ? 8 : 0]);
    uint32_t bBase0 = (uint32_t)__cvta_generic_to_shared(
        &Bs[0][wn * 32 + (lane & 7) + ((lane & 16) ? 8 : 0)][(lane & 8) ? 8 : 0]);
    uint32_t bBase1 = (uint32_t)__cvta_generic_to_shared(
        &Bs[1][wn * 32 + (lane & 7) + ((lane & 16) ? 8 : 0)][(lane & 8) ? 8 : 0]);

    // stage 0: k elements [0, 32)
    {
        *(uint4*)&As[0][rowA][segA * 8]       = *(const uint4*)gA;
        *(uint4*)&Bs[0][rowA][segA * 8]       = *(const uint4*)gB0;
        *(uint4*)&Bs[0][rowA + 128][segA * 8] = *(const uint4*)gB1;
    }
    __syncthreads();

    float c[4][4][4];
    #pragma unroll
    for (int mi = 0; mi < 4; mi++)
        #pragma unroll
        for (int ni = 0; ni < 4; ni++)
            #pragma unroll
            for (int q = 0; q < 4; q++) c[mi][ni][q] = 0.f;

    #pragma unroll 1
    for (int kt = 0; kt < 16; kt++) {            // 16 stages of 32 k
        const int cur = kt & 1;
        uint4 na, nb0, nb1;
        if (kt < 15) {
            na  = *(const uint4*)(gA  + (kt + 1) * 32);
            nb0 = *(const uint4*)(gB0 + (kt + 1) * 32);
            nb1 = *(const uint4*)(gB1 + (kt + 1) * 32);
        }
        const uint32_t aB = cur ? aBase1 : aBase0;
        const uint32_t bB = cur ? bBase1 : bBase0;
        #pragma unroll
        for (int ks = 0; ks < 2; ks++) {         // two 16-k sub-chunks
            const uint32_t ko = ks * 32;         // 16 halves = 32 bytes
            uint32_t af[4][4], bf[4][2];
            #pragma unroll
            for (int mi = 0; mi < 4; mi++)
                ldsm_x4(af[mi][0], af[mi][1], af[mi][2], af[mi][3],
                        aB + mi * 16 * ROWB2 + ko);
            #pragma unroll
            for (int p = 0; p < 2; p++)
                ldsm_x4(bf[2 * p][0], bf[2 * p][1], bf[2 * p + 1][0], bf[2 * p + 1][1],
                        bB + p * 16 * ROWB2 + ko);
            #pragma unroll
            for (int mi = 0; mi < 4; mi++)
                #pragma unroll
                for (int ni = 0; ni < 4; ni++)
                    mma_bf16(c[mi][ni], af[mi], bf[ni]);
        }
        if (kt < 15) {
            *(uint4*)&As[cur ^ 1][rowA][segA * 8]       = na;
            *(uint4*)&Bs[cur ^ 1][rowA][segA * 8]       = nb0;
            *(uint4*)&Bs[cur ^ 1][rowA + 128][segA * 8] = nb1;
        }
        __syncthreads();
    }

    // epilogue: bias + per-tile online-softmax partials (NO logits store)
    #pragma unroll
    for (int mi = 0; mi < 4; mi++) {
        const int mrow = wm * 64 + mi * 16 + g;
        float v0[8], v1[8];
        #pragma unroll
        for (int ni = 0; ni < 4; ni++) {
            int n = nBase + wn * 32 + ni * 8 + 2 * cq;
            bool ok = (n < VV);
            float b0 = ok ? bias[n] : 0.f;
            float b1 = ok ? bias[n + 1] : 0.f;
            v0[ni * 2]     = ok ? (c[mi][ni][0] + b0) : NEGF;
            v0[ni * 2 + 1] = ok ? (c[mi][ni][1] + b1) : NEGF;
            v1[ni * 2]     = ok ? (c[mi][ni][2] + b0) : NEGF;
            v1[ni * 2 + 1] = ok ? (c[mi][ni][3] + b1) : NEGF;
        }
        float mx0 = NEGF, mx1 = NEGF;
        #pragma unroll
        for (int j = 0; j < 8; j++) { mx0 = fmaxf(mx0, v0[j]); mx1 = fmaxf(mx1, v1[j]); }
        float s0 = 0.f, s1 = 0.f;
        #pragma unroll
        for (int j = 0; j < 8; j++) { s0 += __expf(v0[j] - mx0); s1 += __expf(v1[j] - mx1); }
        #pragma unroll
        for (int off = 1; off <= 2; off <<= 1) {
            float om = __shfl_xor_sync(0xffffffffu, mx0, off);
            float os = __shfl_xor_sync(0xffffffffu, s0, off);
            float nm = fmaxf(mx0, om);
            s0 = s0 * __expf(mx0 - nm) + os * __expf(om - nm); mx0 = nm;
            om = __shfl_xor_sync(0xffffffffu, mx1, off);
            os = __shfl_xor_sync(0xffffffffu, s1, off);
            nm = fmaxf(mx1, om);
            s1 = s1 * __expf(mx1 - nm) + os * __expf(om - nm); mx1 = nm;
        }
        if (cq == 0) {
            spmax[mrow][wn] = mx0; spsum[mrow][wn] = s0;
            spmax[mrow + 8][wn] = mx1; spsum[mrow + 8][wn] = s1;
        }
    }
    __syncthreads();
    if (tid < 128) {
        float mx = spmax[tid][0], sm = spsum[tid][0];
        #pragma unroll
        for (int w = 1; w < 8; w++) {
            float m2 = spmax[tid][w], s2 = spsum[tid][w];
            float nm = fmaxf(mx, m2);
            sm = sm * __expf(mx - nm) + s2 * __expf(m2 - nm); mx = nm;
        }
        g_pmax[(size_t)(mBase + tid) * NTILES + blockIdx.x] = mx;
        g_psum[(size_t)(mBase + tid) * NTILES + blockIdx.x] = sm;
    }
}

// ------------------------- combine partials -> row lse ---------------------
__global__ __launch_bounds__(256) void lsecombine_kernel() {
    int row = blockIdx.x * 8 + (threadIdx.x >> 5);
    int lane = threadIdx.x & 31;
    float mx = NEGF, sm = 0.f;
    if (lane < NTILES) {
        mx = g_pmax[(size_t)row * NTILES + lane];
        sm = g_psum[(size_t)row * NTILES + lane];
    }
    #pragma unroll
    for (int o = 16; o > 0; o >>= 1) {
        float m2 = __shfl_xor_sync(0xffffffffu, mx, o);
        float s2 = __shfl_xor_sync(0xffffffffu, sm, o);
        float nm = fmaxf(mx, m2);
        sm = sm * __expf(mx - nm) + s2 * __expf(m2 - nm); mx = nm;
    }
    if (lane == 0) g_lse[row] = mx + __logf(sm);
}

// ------------------------- small GEMM: compact label logits ----------------
// lgc[b][m][j] = hs[b,m,:] . Wc[b,j,:] + biasc[b][j]
__global__ __launch_bounds__(256) void lgc_kernel() {
    const int tid  = threadIdx.x;
    const int warp = tid >> 5, lane = tid & 31;
    const int wm = warp >> 1, wn = warp & 1;       // 4x2 warp grid
    const int g  = lane >> 2, cq = lane & 3;
    const int b = blockIdx.x;
    const int mBase = blockIdx.y * 128;

    __shared__ __nv_bfloat16 As[2][128][24];
    __shared__ __nv_bfloat16 Bs[2][NT][24];

    const int row = tid >> 1, half = tid & 1;
    const __nv_bfloat16* gA = g_hsb + ((size_t)b * TT + mBase + row) * DD + half * 8;
    const int bidx2 = tid + 256;
    const __nv_bfloat16* gB0 = g_Wc + ((size_t)b * NT + (tid >> 1)) * DD + (tid & 1) * 8;
    const __nv_bfloat16* gB1 = g_Wc + ((size_t)b * NT + (bidx2 >> 1)) * DD + (bidx2 & 1) * 8;

    uint32_t aBase0 = (uint32_t)__cvta_generic_to_shared(
        &As[0][wm * 32 + (lane & 15)][(lane & 16) ? 8 : 0]);
    uint32_t aBase1 = (uint32_t)__cvta_generic_to_shared(
        &As[1][wm * 32 + (lane & 15)][(lane & 16) ? 8 : 0]);
    uint32_t bBase0 = (uint32_t)__cvta_generic_to_shared(
        &Bs[0][wn * 80 + (lane & 7) + ((lane & 16) ? 8 : 0)][(lane & 8) ? 8 : 0]);
    uint32_t bBase1 = (uint32_t)__cvta_generic_to_shared(
        &Bs[1][wn * 80 + (lane & 7) + ((lane & 16) ? 8 : 0)][(lane & 8) ? 8 : 0]);

    {
        *(uint4*)&As[0][row][half * 8] = *(const uint4*)gA;
        *(uint4*)&Bs[0][tid >> 1][(tid & 1) * 8] = *(const uint4*)gB0;
        if (tid < 64)
            *(uint4*)&Bs[0][bidx2 >> 1][(bidx2 & 1) * 8] = *(const uint4*)gB1;
    }
    __syncthreads();

    float c[2][10][4];
    #pragma unroll
    for (int mi = 0; mi < 2; mi++)
        #pragma unroll
        for (int ni = 0; ni < 10; ni++)
            #pragma unroll
            for (int q = 0; q < 4; q++) c[mi][ni][q] = 0.f;

    #pragma unroll 1
    for (int kt = 0; kt < 32; kt++) {
        const int cur = kt & 1;
        uint4 na, nb0, nb1;
        if (kt < 31) {
            na  = *(const uint4*)(gA + (kt + 1) * 16);
            nb0 = *(const uint4*)(gB0 + (kt + 1) * 16);
            if (tid < 64) nb1 = *(const uint4*)(gB1 + (kt + 1) * 16);
        }
        const uint32_t aB = cur ? aBase1 : aBase0;
        const uint32_t bB = cur ? bBase1 : bBase0;
        uint32_t af[2][4], bf[10][2];
        #pragma unroll
        for (int mi = 0; mi < 2; mi++)
            ldsm_x4(af[mi][0], af[mi][1], af[mi][2], af[mi][3], aB + mi * 16 * ROWB);
        #pragma unroll
        for (int p = 0; p < 5; p++)
            ldsm_x4(bf[2 * p][0], bf[2 * p][1], bf[2 * p + 1][0], bf[2 * p + 1][1],
                    bB + p * 16 * ROWB);
        #pragma unroll
        for (int mi = 0; mi < 2; mi++)
            #pragma unroll
            for (int ni = 0; ni < 10; ni++)
                mma_bf16(c[mi][ni], af[mi], bf[ni]);

        if (kt < 31) {
            *(uint4*)&As[cur ^ 1][row][half * 8] = na;
            *(uint4*)&Bs[cur ^ 1][tid >> 1][(tid & 1) * 8] = nb0;
            if (tid < 64)
                *(uint4*)&Bs[cur ^ 1][bidx2 >> 1][(bidx2 & 1) * 8] = nb1;
        }
        __syncthreads();
    }

    float* lgb = g_lgc + ((size_t)b * TT + mBase) * NT;
    #pragma unroll
    for (int mi = 0; mi < 2; mi++) {
        int mrow = wm * 32 + mi * 16 + g;
        #pragma unroll
        for (int ni = 0; ni < 10; ni++) {
            int j = wn * 80 + ni * 8 + 2 * cq;
            float b0 = g_biasc[b * NT + j], b1 = g_biasc[b * NT + j + 1];
            *(float2*)&lgb[(size_t)mrow * NT + j] =
                make_float2(c[mi][ni][0] + b0, c[mi][ni][1] + b1);
            *(float2*)&lgb[(size_t)(mrow + 8) * NT + j] =
                make_float2(c[mi][ni][2] + b0, c[mi][ni][3] + b1);
        }
    }
}

// ------------------------- CTC forward recursion ---------------------------
// log2 domain; gather fused (reads g_lgc/g_lse directly); depth-2 load
// prefetch ring to cover L2 latency; 3-MUFU lse3 (max term contributes 1).
__global__ __launch_bounds__(288) void ctc_kernel(const int* __restrict__ hlens,
                                                  const int* __restrict__ ys_lens) {
    const int b = blockIdx.x;
    const int s = threadIdx.x;
    const bool act = (s < SS);
    __shared__ float aS[2][SS + 4];   // index shift +2; pads hold NEGF

    const int hlen = hlens[b];
    const int alw = act ? g_allow[b * SS + s] : 0;
    const int j = (s & 1) ? (1 + (s >> 1)) : 0;
    const float* __restrict__ lgb  = g_lgc + (size_t)b * TT * NT + j;
    const float* __restrict__ lseb = g_lse + b * TT;

    if (s < 2) { aS[0][s] = NEGF; aS[1][s] = NEGF; }
    if (act) {
        float lp0 = (lgb[0] - lseb[0]) * LOG2E;
        aS[0][s + 2] = (s < 2) ? lp0 : NEGF;
    }
    __syncthreads();

    // prefetch ring: (la1,le1) for t, (la2,le2) for t+1
    float la1 = act ? lgb[(size_t)NT] : 0.f;
    float le1 = lseb[1];
    float la2 = 0.f, le2 = 0.f;
    if (2 < hlen) { la2 = act ? lgb[(size_t)2 * NT] : 0.f; le2 = lseb[2]; }

    int cur = 0;
    for (int t = 1; t < hlen; t++) {
        float la3 = 0.f, le3 = 0.f;
        if (t + 2 < hlen) {
            la3 = act ? lgb[(size_t)(t + 2) * NT] : 0.f;
            le3 = lseb[t + 2];
        }
        if (act) {
            float a1 = aS[cur][s + 2];
            float a2 = aS[cur][s + 1];
            float a3 = alw ? aS[cur][s] : NEGF;
            // sorted lse3: m = max, {q,y} = the two non-max values
            float p = fmaxf(a1, a2), q = fminf(a1, a2);
            float m = fmaxf(p, a3), y = fminf(p, a3);
            float lp_c = (la1 - le1) * LOG2E;
            float nv = m + flg2(1.0f + fex2(q - m) + fex2(y - m)) + lp_c;
            aS[cur ^ 1][s + 2] = nv;
        }
        __syncthreads();
        cur ^= 1;
        la1 = la2; le1 = le2; la2 = la3; le2 = le3;
    }

    if (s == 0) {
        int yl = ys_lens[b];
        int i1 = 2 * yl;
        int i2 = (i1 - 1 > 0) ? (i1 - 1) : 0;
        float A1 = aS[cur][i1 + 2];
        float A2 = aS[cur][i2 + 2];
        float m = fmaxf(A1, A2);
        float ll = (m + flg2(fex2(A1 - m) + fex2(A2 - m))) * LN2F;
        float loss = -ll;
        if (!isfinite(loss) || loss >= 1e29f) loss = 0.f;
        g_loss[b] = loss;
    }
}

// ------------------------- final reduction ---------------------------------
__global__ void final_kernel(const int* __restrict__ ys_lens, float* __restrict__ out) {
    int lane = threadIdx.x;
    float l  = (lane < BB) ? g_loss[lane] : 0.f;
    float yl = (lane < BB) ? (float)ys_lens[lane] : 0.f;
    #pragma unroll
    for (int o = 16; o > 0; o >>= 1) {
        l  += __shfl_down_sync(0xffffffffu, l, o);
        yl += __shfl_down_sync(0xffffffffu, yl, o);
    }
    if (lane == 0) out[0] = l / yl;
}

// ------------------------- launch ------------------------------------------
extern "C" void kernel_launch(void* const* d_in, const int* in_sizes, int n_in,
                              void* d_out, int out_size) {
    const float* hs      = (const float*)d_in[0];
    const int*   hlens   = (const int*)d_in[1];
    const int*   ys_pad  = (const int*)d_in[2];
    const int*   ys_lens = (const int*)d_in[3];
    const float* W       = (const float*)d_in[4];
    const float* bias    = (const float*)d_in[5];
    float* out = (float*)d_out;

    conv_hs_kernel<<<(MM * DD / 4) / 256, 256>>>(hs);          // #1
    {
        dim3 wgrid((VV + 31) / 32, DD / 32);
        conv_w_kernel<<<wgrid, dim3(32, 8)>>>(W);              // #2
    }
    ext_kernel<<<BB, 288>>>(ys_pad);                           // #3

    dim3 ggrid(NPAD / 256, MM / 128);                          // #4  (profiled slot)
    gemm_kernel<<<ggrid, 512>>>(bias);

    lsecombine_kernel<<<MM / 8, 256>>>();                      // #5

    prep_wc_kernel<<<dim3(BB, 129), 64>>>(ys_pad, bias);       // #6

    lgc_kernel<<<dim3(BB, TT / 128), 256>>>();                 // #7

    ctc_kernel<<<BB, 288>>>(hlens, ys_lens);                   // #8
    final_kernel<<<1, 32>>>(ys_lens, out);                     // #9
}

// round 17
// speedup vs baseline: 1.2740x; 1.0322x over previous
#include <cuda_runtime.h>
#include <cuda_bf16.h>
#include <cstdint>
#include <math.h>

// Problem dims (fixed by the dataset)
#define BB 16
#define TT 1024
#define DD 512
#define VV 5000
#define LL 128
#define SS 257              // 2L+1
#define MM (BB*TT)          // 16384 rows
#define NPAD 5120           // padded N
#define NTILES 20           // NPAD/256 (n-tiles of 256)
#define NT 160              // compact label-logit width (129 used, padded)
#define NEGF (-1e30f)
#define LOG2E 1.4426950408889634f
#define LN2F 0.6931471805599453f

// ------------------------- scratch (device globals; zero-initialized) ------
__device__ __nv_bfloat16 g_hsb[(size_t)MM * DD];          // 16.8 MB
__device__ __nv_bfloat16 g_Wb[(size_t)NPAD * DD];         // 5.2 MB (rows >=5000 stay zero)
__device__ float g_lgc[(size_t)BB * TT * NT];             // compact label logits
__device__ float g_pmax[(size_t)MM * NTILES];
__device__ float g_psum[(size_t)MM * NTILES];
__device__ float g_lse[MM];
__device__ float g_loss[BB];

// ------------------------- helpers -----------------------------------------
__device__ __forceinline__ float fex2(float x) {
    float y; asm("ex2.approx.ftz.f32 %0, %1;" : "=f"(y) : "f"(x)); return y;
}
__device__ __forceinline__ float flg2(float x) {
    float y; asm("lg2.approx.f32 %0, %1;" : "=f"(y) : "f"(x)); return y;
}

// ------------------------- conversions -------------------------------------
__global__ void conv_hs_kernel(const float* __restrict__ hs) {
    size_t i = (size_t)blockIdx.x * blockDim.x + threadIdx.x;   // over MM*DD/4
    float4 v = ((const float4*)hs)[i];
    __nv_bfloat162* o = reinterpret_cast<__nv_bfloat162*>(g_hsb) + i * 2;
    o[0] = __floats2bfloat162_rn(v.x, v.y);
    o[1] = __floats2bfloat162_rn(v.z, v.w);
}

// W (D,V) row-major -> Wb[n][k] bf16, transposed through shared tiles
__global__ void conv_w_kernel(const float* __restrict__ W) {
    __shared__ float tile[32][33];
    int nt = blockIdx.x * 32, kt = blockIdx.y * 32;
    int tx = threadIdx.x, ty = threadIdx.y;     // 32 x 8
    #pragma unroll
    for (int i = 0; i < 32; i += 8) {
        int k = kt + ty + i, n = nt + tx;
        tile[ty + i][tx] = (n < VV) ? W[(size_t)k * VV + n] : 0.f;
    }
    __syncthreads();
    #pragma unroll
    for (int i = 0; i < 32; i += 8) {
        int n = nt + ty + i, k = kt + tx;
        if (n < VV)
            g_Wb[(size_t)n * DD + k] = __float2bfloat16(tile[tx][ty + i]);
    }
}

// ------------------------- mma / ldmatrix helpers --------------------------
__device__ __forceinline__ void mma_bf16(float* c, const uint32_t* a, const uint32_t* b) {
    asm volatile(
        "mma.sync.aligned.m16n8k16.row.col.f32.bf16.bf16.f32 "
        "{%0,%1,%2,%3}, {%4,%5,%6,%7}, {%8,%9}, {%0,%1,%2,%3};\n"
        : "+f"(c[0]), "+f"(c[1]), "+f"(c[2]), "+f"(c[3])
        : "r"(a[0]), "r"(a[1]), "r"(a[2]), "r"(a[3]), "r"(b[0]), "r"(b[1]));
}
__device__ __forceinline__ void ldsm_x4(uint32_t& r0, uint32_t& r1, uint32_t& r2, uint32_t& r3,
                                        uint32_t addr) {
    asm volatile("ldmatrix.sync.aligned.m8n8.x4.shared.b16 {%0,%1,%2,%3}, [%4];\n"
                 : "=r"(r0), "=r"(r1), "=r"(r2), "=r"(r3) : "r"(addr));
}

#define ROWB 48    // lgc kernel: 24 halves * 2 bytes per smem row
#define ROWB2 80   // main gemm: 40 halves * 2 bytes per smem row (32-k stage)

// ------------------------- main GEMM: lse partials only --------------------
// 128x256 block tile, 512 threads (2x8 warp grid, warp tile 64x32),
// 32-k double-buffered stages, register staging (proven R8 config).
__global__ __launch_bounds__(512) void gemm_kernel(const float* __restrict__ bias) {
    const int tid  = threadIdx.x;
    const int warp = tid >> 5, lane = tid & 31;
    const int wm = warp >> 3, wn = warp & 7;       // 2x8 warp grid
    const int g  = lane >> 2, cq = lane & 3;       // groupID / quad
    const int mBase = blockIdx.y * 128;
    const int nBase = blockIdx.x * 256;

    __shared__ __nv_bfloat16 As[2][128][40];       // 32 k + 8 pad halves
    __shared__ __nv_bfloat16 Bs[2][256][40];
    __shared__ float spmax[128][8];
    __shared__ float spsum[128][8];

    // staging: A one 16B seg per thread, B two
    const int rowA = tid >> 2, segA = tid & 3;     // 128 rows x 4 segs
    const __nv_bfloat16* gA  = g_hsb + (size_t)(mBase + rowA) * DD + segA * 8;
    const __nv_bfloat16* gB0 = g_Wb  + (size_t)(nBase + rowA) * DD + segA * 8;
    const __nv_bfloat16* gB1 = g_Wb  + (size_t)(nBase + rowA + 128) * DD + segA * 8;

    // ldmatrix base addresses (per lane); mi/p and k-sub-chunk offsets in-loop
    uint32_t aBase0 = (uint32_t)__cvta_generic_to_shared(
        &As[0][wm * 64 + (lane & 15)][(lane & 16) ? 8 : 0]);
    uint32_t aBase1 = (uint32_t)__cvta_generic_to_shared(
        &As[1][wm * 64 + (lane & 15)][(lane & 16) ? 8 : 0]);
    uint32_t bBase0 = (uint32_t)__cvta_generic_to_shared(
        &Bs[0][wn * 32 + (lane & 7) + ((lane & 16) ? 8 : 0)][(lane & 8) ? 8 : 0]);
    uint32_t bBase1 = (uint32_t)__cvta_generic_to_shared(
        &Bs[1][wn * 32 + (lane & 7) + ((lane & 16) ? 8 : 0)][(lane & 8) ? 8 : 0]);

    // stage 0: k elements [0, 32)
    {
        *(uint4*)&As[0][rowA][segA * 8]       = *(const uint4*)gA;
        *(uint4*)&Bs[0][rowA][segA * 8]       = *(const uint4*)gB0;
        *(uint4*)&Bs[0][rowA + 128][segA * 8] = *(const uint4*)gB1;
    }
    __syncthreads();

    float c[4][4][4];
    #pragma unroll
    for (int mi = 0; mi < 4; mi++)
        #pragma unroll
        for (int ni = 0; ni < 4; ni++)
            #pragma unroll
            for (int q = 0; q < 4; q++) c[mi][ni][q] = 0.f;

    #pragma unroll 1
    for (int kt = 0; kt < 16; kt++) {            // 16 stages of 32 k
        const int cur = kt & 1;
        uint4 na, nb0, nb1;
        if (kt < 15) {
            na  = *(const uint4*)(gA  + (kt + 1) * 32);
            nb0 = *(const uint4*)(gB0 + (kt + 1) * 32);
            nb1 = *(const uint4*)(gB1 + (kt + 1) * 32);
        }
        const uint32_t aB = cur ? aBase1 : aBase0;
        const uint32_t bB = cur ? bBase1 : bBase0;
        #pragma unroll
        for (int ks = 0; ks < 2; ks++) {         // two 16-k sub-chunks
            const uint32_t ko = ks * 32;         // 16 halves = 32 bytes
            uint32_t af[4][4], bf[4][2];
            #pragma unroll
            for (int mi = 0; mi < 4; mi++)
                ldsm_x4(af[mi][0], af[mi][1], af[mi][2], af[mi][3],
                        aB + mi * 16 * ROWB2 + ko);
            #pragma unroll
            for (int p = 0; p < 2; p++)
                ldsm_x4(bf[2 * p][0], bf[2 * p][1], bf[2 * p + 1][0], bf[2 * p + 1][1],
                        bB + p * 16 * ROWB2 + ko);
            #pragma unroll
            for (int mi = 0; mi < 4; mi++)
                #pragma unroll
                for (int ni = 0; ni < 4; ni++)
                    mma_bf16(c[mi][ni], af[mi], bf[ni]);
        }
        if (kt < 15) {
            *(uint4*)&As[cur ^ 1][rowA][segA * 8]       = na;
            *(uint4*)&Bs[cur ^ 1][rowA][segA * 8]       = nb0;
            *(uint4*)&Bs[cur ^ 1][rowA + 128][segA * 8] = nb1;
        }
        __syncthreads();
    }

    // epilogue: bias + per-tile online-softmax partials (NO logits store)
    #pragma unroll
    for (int mi = 0; mi < 4; mi++) {
        const int mrow = wm * 64 + mi * 16 + g;
        float v0[8], v1[8];
        #pragma unroll
        for (int ni = 0; ni < 4; ni++) {
            int n = nBase + wn * 32 + ni * 8 + 2 * cq;
            bool ok = (n < VV);
            float b0 = ok ? bias[n] : 0.f;
            float b1 = ok ? bias[n + 1] : 0.f;
            v0[ni * 2]     = ok ? (c[mi][ni][0] + b0) : NEGF;
            v0[ni * 2 + 1] = ok ? (c[mi][ni][1] + b1) : NEGF;
            v1[ni * 2]     = ok ? (c[mi][ni][2] + b0) : NEGF;
            v1[ni * 2 + 1] = ok ? (c[mi][ni][3] + b1) : NEGF;
        }
        float mx0 = NEGF, mx1 = NEGF;
        #pragma unroll
        for (int j = 0; j < 8; j++) { mx0 = fmaxf(mx0, v0[j]); mx1 = fmaxf(mx1, v1[j]); }
        float s0 = 0.f, s1 = 0.f;
        #pragma unroll
        for (int j = 0; j < 8; j++) { s0 += __expf(v0[j] - mx0); s1 += __expf(v1[j] - mx1); }
        #pragma unroll
        for (int off = 1; off <= 2; off <<= 1) {
            float om = __shfl_xor_sync(0xffffffffu, mx0, off);
            float os = __shfl_xor_sync(0xffffffffu, s0, off);
            float nm = fmaxf(mx0, om);
            s0 = s0 * __expf(mx0 - nm) + os * __expf(om - nm); mx0 = nm;
            om = __shfl_xor_sync(0xffffffffu, mx1, off);
            os = __shfl_xor_sync(0xffffffffu, s1, off);
            nm = fmaxf(mx1, om);
            s1 = s1 * __expf(mx1 - nm) + os * __expf(om - nm); mx1 = nm;
        }
        if (cq == 0) {
            spmax[mrow][wn] = mx0; spsum[mrow][wn] = s0;
            spmax[mrow + 8][wn] = mx1; spsum[mrow + 8][wn] = s1;
        }
    }
    __syncthreads();
    if (tid < 128) {
        float mx = spmax[tid][0], sm = spsum[tid][0];
        #pragma unroll
        for (int w = 1; w < 8; w++) {
            float m2 = spmax[tid][w], s2 = spsum[tid][w];
            float nm = fmaxf(mx, m2);
            sm = sm * __expf(mx - nm) + s2 * __expf(m2 - nm); mx = nm;
        }
        g_pmax[(size_t)(mBase + tid) * NTILES + blockIdx.x] = mx;
        g_psum[(size_t)(mBase + tid) * NTILES + blockIdx.x] = sm;
    }
}

// ------------------------- combine partials -> row lse ---------------------
__global__ __launch_bounds__(256) void lsecombine_kernel() {
    int row = blockIdx.x * 8 + (threadIdx.x >> 5);
    int lane = threadIdx.x & 31;
    float mx = NEGF, sm = 0.f;
    if (lane < NTILES) {
        mx = g_pmax[(size_t)row * NTILES + lane];
        sm = g_psum[(size_t)row * NTILES + lane];
    }
    #pragma unroll
    for (int o = 16; o > 0; o >>= 1) {
        float m2 = __shfl_xor_sync(0xffffffffu, mx, o);
        float s2 = __shfl_xor_sync(0xffffffffu, sm, o);
        float nm = fmaxf(mx, m2);
        sm = sm * __expf(mx - nm) + s2 * __expf(m2 - nm); mx = nm;
    }
    if (lane == 0) g_lse[row] = mx + __logf(sm);
}

// ------------------------- small GEMM: compact label logits ----------------
// lgc[b][m][j] = hs[b,m,:] . W[:,lab_j] + bias[lab_j]; labels gathered in-kernel
__global__ __launch_bounds__(256) void lgc_kernel(const int* __restrict__ ys_pad,
                                                  const float* __restrict__ bias) {
    const int tid  = threadIdx.x;
    const int warp = tid >> 5, lane = tid & 31;
    const int wm = warp >> 1, wn = warp & 1;       // 4x2 warp grid
    const int g  = lane >> 2, cq = lane & 3;
    const int b = blockIdx.x;
    const int mBase = blockIdx.y * 128;

    __shared__ __nv_bfloat16 As[2][128][24];
    __shared__ __nv_bfloat16 Bs[2][NT][24];
    __shared__ int labs[NT];

    if (tid < NT) {
        int lab = 0;
        if (tid >= 1 && tid < 129) lab = ys_pad[b * LL + tid - 1];
        labs[tid] = lab;
    }
    __syncthreads();

    const int row = tid >> 1, half = tid & 1;
    const __nv_bfloat16* gA = g_hsb + ((size_t)b * TT + mBase + row) * DD + half * 8;
    const int bidx2 = tid + 256;
    // SAFE index: labs has NT=160 entries; bidx2>>1 would be 160..255 for
    // tid>=64 (OOB shared read). Only tid<64 ever dereferences gB1.
    const int idx2 = (tid < 64) ? (bidx2 >> 1) : 0;
    const __nv_bfloat16* gB0 = g_Wb + (size_t)labs[tid >> 1] * DD + (tid & 1) * 8;
    const __nv_bfloat16* gB1 = g_Wb + (size_t)labs[idx2] * DD + (tid & 1) * 8;

    uint32_t aBase0 = (uint32_t)__cvta_generic_to_shared(
        &As[0][wm * 32 + (lane & 15)][(lane & 16) ? 8 : 0]);
    uint32_t aBase1 = (uint32_t)__cvta_generic_to_shared(
        &As[1][wm * 32 + (lane & 15)][(lane & 16) ? 8 : 0]);
    uint32_t bBase0 = (uint32_t)__cvta_generic_to_shared(
        &Bs[0][wn * 80 + (lane & 7) + ((lane & 16) ? 8 : 0)][(lane & 8) ? 8 : 0]);
    uint32_t bBase1 = (uint32_t)__cvta_generic_to_shared(
        &Bs[1][wn * 80 + (lane & 7) + ((lane & 16) ? 8 : 0)][(lane & 8) ? 8 : 0]);

    {
        *(uint4*)&As[0][row][half * 8] = *(const uint4*)gA;
        *(uint4*)&Bs[0][tid >> 1][(tid & 1) * 8] = *(const uint4*)gB0;
        if (tid < 64)
            *(uint4*)&Bs[0][bidx2 >> 1][(tid & 1) * 8] = *(const uint4*)gB1;
    }
    __syncthreads();

    float c[2][10][4];
    #pragma unroll
    for (int mi = 0; mi < 2; mi++)
        #pragma unroll
        for (int ni = 0; ni < 10; ni++)
            #pragma unroll
            for (int q = 0; q < 4; q++) c[mi][ni][q] = 0.f;

    #pragma unroll 1
    for (int kt = 0; kt < 32; kt++) {
        const int cur = kt & 1;
        uint4 na, nb0, nb1;
        if (kt < 31) {
            na  = *(const uint4*)(gA + (kt + 1) * 16);
            nb0 = *(const uint4*)(gB0 + (kt + 1) * 16);
            if (tid < 64) nb1 = *(const uint4*)(gB1 + (kt + 1) * 16);
        }
        const uint32_t aB = cur ? aBase1 : aBase0;
        const uint32_t bB = cur ? bBase1 : bBase0;
        uint32_t af[2][4], bf[10][2];
        #pragma unroll
        for (int mi = 0; mi < 2; mi++)
            ldsm_x4(af[mi][0], af[mi][1], af[mi][2], af[mi][3], aB + mi * 16 * ROWB);
        #pragma unroll
        for (int p = 0; p < 5; p++)
            ldsm_x4(bf[2 * p][0], bf[2 * p][1], bf[2 * p + 1][0], bf[2 * p + 1][1],
                    bB + p * 16 * ROWB);
        #pragma unroll
        for (int mi = 0; mi < 2; mi++)
            #pragma unroll
            for (int ni = 0; ni < 10; ni++)
                mma_bf16(c[mi][ni], af[mi], bf[ni]);

        if (kt < 31) {
            *(uint4*)&As[cur ^ 1][row][half * 8] = na;
            *(uint4*)&Bs[cur ^ 1][tid >> 1][(tid & 1) * 8] = nb0;
            if (tid < 64)
                *(uint4*)&Bs[cur ^ 1][bidx2 >> 1][(tid & 1) * 8] = nb1;
        }
        __syncthreads();
    }

    float* lgb = g_lgc + ((size_t)b * TT + mBase) * NT;
    #pragma unroll
    for (int mi = 0; mi < 2; mi++) {
        int mrow = wm * 32 + mi * 16 + g;
        #pragma unroll
        for (int ni = 0; ni < 10; ni++) {
            int j = wn * 80 + ni * 8 + 2 * cq;
            float b0 = bias[labs[j]], b1 = bias[labs[j + 1]];
            *(float2*)&lgb[(size_t)mrow * NT + j] =
                make_float2(c[mi][ni][0] + b0, c[mi][ni][1] + b1);
            *(float2*)&lgb[(size_t)(mrow + 8) * NT + j] =
                make_float2(c[mi][ni][2] + b0, c[mi][ni][3] + b1);
        }
    }
}

// ------------------------- CTC forward recursion ---------------------------
// log2 domain; gather + allow fused; depth-2 prefetch; 3-MUFU lse3;
// state clamp s <= 2*ys_len (higher states never reach the read-out).
__global__ __launch_bounds__(288) void ctc_kernel(const int* __restrict__ hlens,
                                                  const int* __restrict__ ys_lens,
                                                  const int* __restrict__ ys_pad) {
    const int b = blockIdx.x;
    const int s = threadIdx.x;
    const int hlen = hlens[b];
    const int yl = ys_lens[b];
    const bool act = (s < SS) && (s <= 2 * yl);
    __shared__ float aS[2][SS + 4];   // index shift +2; pads hold NEGF

    int alw = 0;
    if (act && (s & 1)) {
        int i = s >> 1;
        int im1 = (i >= 1) ? (i - 1) : 0;    // clamped: both loads always in-bounds
        int curlab = ys_pad[b * LL + i];
        int prvlab = ys_pad[b * LL + im1];
        alw = (s == 1) ? 1 : (curlab != prvlab);
    }
    const int j = (s & 1) ? (1 + (s >> 1)) : 0;
    const float* __restrict__ lgb  = g_lgc + (size_t)b * TT * NT + j;
    const float* __restrict__ lseb = g_lse + b * TT;

    if (s < 2) { aS[0][s] = NEGF; aS[1][s] = NEGF; }
    if (s < SS) {
        float lp0 = (s < 2) ? (lgb[0] - lseb[0]) * LOG2E : NEGF;
        aS[0][s + 2] = lp0;
        aS[1][s + 2] = NEGF;
    }
    __syncthreads();

    // prefetch ring: (la1,le1) for t, (la2,le2) for t+1
    float la1 = act ? lgb[(size_t)NT] : 0.f;
    float le1 = lseb[1];
    float la2 = 0.f, le2 = 0.f;
    if (2 < hlen) { la2 = act ? lgb[(size_t)2 * NT] : 0.f; le2 = lseb[2]; }

    int cur = 0;
    for (int t = 1; t < hlen; t++) {
        float la3 = 0.f, le3 = 0.f;
        if (t + 2 < hlen) {
            la3 = act ? lgb[(size_t)(t + 2) * NT] : 0.f;
            le3 = lseb[t + 2];
        }
        if (act) {
            float a1 = aS[cur][s + 2];
            float a2 = aS[cur][s + 1];
            float a3 = alw ? aS[cur][s] : NEGF;
            // sorted lse3: m = max, {q,y} = the two non-max values
            float p = fmaxf(a1, a2), q = fminf(a1, a2);
            float m = fmaxf(p, a3), y = fminf(p, a3);
            float lp_c = (la1 - le1) * LOG2E;
            float nv = m + flg2(1.0f + fex2(q - m) + fex2(y - m)) + lp_c;
            aS[cur ^ 1][s + 2] = nv;
        }
        __syncthreads();
        cur ^= 1;
        la1 = la2; le1 = le2; la2 = la3; le2 = le3;
    }

    if (s == 0) {
        int i1 = 2 * yl;
        int i2 = (i1 - 1 > 0) ? (i1 - 1) : 0;
        float A1 = aS[cur][i1 + 2];
        float A2 = aS[cur][i2 + 2];
        float m = fmaxf(A1, A2);
        float ll = (m + flg2(fex2(A1 - m) + fex2(A2 - m))) * LN2F;
        float loss = -ll;
        if (!isfinite(loss) || loss >= 1e29f) loss = 0.f;
        g_loss[b] = loss;
    }
}

// ------------------------- final reduction ---------------------------------
__global__ void final_kernel(const int* __restrict__ ys_lens, float* __restrict__ out) {
    int lane = threadIdx.x;
    float l  = (lane < BB) ? g_loss[lane] : 0.f;
    float yl = (lane < BB) ? (float)ys_lens[lane] : 0.f;
    #pragma unroll
    for (int o = 16; o > 0; o >>= 1) {
        l  += __shfl_down_sync(0xffffffffu, l, o);
        yl += __shfl_down_sync(0xffffffffu, yl, o);
    }
    if (lane == 0) out[0] = l / yl;
}

// ------------------------- launch ------------------------------------------
extern "C" void kernel_launch(void* const* d_in, const int* in_sizes, int n_in,
                              void* d_out, int out_size) {
    const float* hs      = (const float*)d_in[0];
    const int*   hlens   = (const int*)d_in[1];
    const int*   ys_pad  = (const int*)d_in[2];
    const int*   ys_lens = (const int*)d_in[3];
    const float* W       = (const float*)d_in[4];
    const float* bias    = (const float*)d_in[5];
    float* out = (float*)d_out;

    conv_hs_kernel<<<(MM * DD / 4) / 256, 256>>>(hs);          // #1
    {
        dim3 wgrid((VV + 31) / 32, DD / 32);
        conv_w_kernel<<<wgrid, dim3(32, 8)>>>(W);              // #2
    }

    dim3 ggrid(NPAD / 256, MM / 128);                          // #3
    gemm_kernel<<<ggrid, 512>>>(bias);

    lsecombine_kernel<<<MM / 8, 256>>>();                      // #4

    lgc_kernel<<<dim3(BB, TT / 128), 256>>>(ys_pad, bias);     // #5

    ctc_kernel<<<BB, 288>>>(hlens, ys_lens, ys_pad);           // #6
    final_kernel<<<1, 32>>>(ys_lens, out);                     // #7
}